// round 1
// baseline (speedup 1.0000x reference)
#include <cuda_runtime.h>
#include <cstdint>

#define B_  4
#define L_  2048
#define H_  512
#define NH  8
#define D_  64

// ---------------- scratch (static device globals; no allocation) ----------------
__device__ float g_Q[B_*NH*L_*D_];      // 16 MB, head layout (b,h,l,d), pre-scaled
__device__ float g_K[B_*NH*L_*D_];      // 16 MB
__device__ float g_V[B_*NH*L_*D_];      // 16 MB
__device__ float g_Diag[B_*NH*L_];      // softmax diagonal values
__device__ float g_Opre[B_*L_*H_];      // 16 MB, (b,l,h*64+d) = diag * v

// ---------------- Kernel 1: fused QKV projection GEMMs --------------------------
// C = A(M,K) @ W(N,K)^T + bias, written into head layout. M=8192,N=512,K=512.
// 64x64 tile, BK=16, 256 threads, 4x4 microtile.
__global__ __launch_bounds__(256)
void gemm_qkv_kernel(const float* __restrict__ q_in, const float* __restrict__ k_in,
                     const float* __restrict__ v_in,
                     const float* __restrict__ Wq, const float* __restrict__ bq,
                     const float* __restrict__ Wk, const float* __restrict__ bk,
                     const float* __restrict__ Wv, const float* __restrict__ bv)
{
    const float* A; const float* W; const float* bias; float* Cout; float scale;
    int mode = blockIdx.z;
    if (mode == 0)      { A = q_in; W = Wq; bias = bq; Cout = g_Q; scale = 0.125f; }
    else if (mode == 1) { A = k_in; W = Wk; bias = bk; Cout = g_K; scale = 1.0f;   }
    else                { A = v_in; W = Wv; bias = bv; Cout = g_V; scale = 1.0f;   }

    __shared__ float As[16][68];
    __shared__ float Bs[16][68];

    int tid = threadIdx.x;
    int tx = tid & 15, ty = tid >> 4;
    int m0 = blockIdx.y * 64;
    int n0 = blockIdx.x * 64;

    int lr = tid >> 2;          // 0..63
    int lc = (tid & 3) * 4;     // 0,4,8,12

    float acc[4][4] = {};

    for (int k0 = 0; k0 < H_; k0 += 16) {
        float4 av = *(const float4*)&A[(size_t)(m0 + lr) * H_ + k0 + lc];
        float4 wv = *(const float4*)&W[(size_t)(n0 + lr) * H_ + k0 + lc];
        As[lc+0][lr] = av.x; As[lc+1][lr] = av.y; As[lc+2][lr] = av.z; As[lc+3][lr] = av.w;
        Bs[lc+0][lr] = wv.x; Bs[lc+1][lr] = wv.y; Bs[lc+2][lr] = wv.z; Bs[lc+3][lr] = wv.w;
        __syncthreads();
        #pragma unroll
        for (int kk = 0; kk < 16; kk++) {
            float4 a = *(const float4*)&As[kk][ty*4];
            float4 b = *(const float4*)&Bs[kk][tx*4];
            float ar[4] = {a.x, a.y, a.z, a.w};
            float br[4] = {b.x, b.y, b.z, b.w};
            #pragma unroll
            for (int i = 0; i < 4; i++)
                #pragma unroll
                for (int j = 0; j < 4; j++) acc[i][j] += ar[i] * br[j];
        }
        __syncthreads();
    }

    #pragma unroll
    for (int i = 0; i < 4; i++) {
        int row = m0 + ty*4 + i;
        int b   = row >> 11;          // /2048
        int ii  = row & (L_ - 1);
        #pragma unroll
        for (int j = 0; j < 4; j++) {
            int n = n0 + tx*4 + j;
            int h = n >> 6, d = n & 63;
            Cout[(((size_t)(b*NH + h) * L_ + ii) * D_) + d] = (acc[i][j] + bias[n]) * scale;
        }
    }
}

// ---------------- Kernel 2: fused scores + relative-pos + online-softmax diag ---
// Block: 32 query rows (one head). Loop over 128-wide j tiles.
// s[i,j] = q_i.k_j + q_i.Wp[j-i+2047] + Wp_b[j-i+2047]
// Only row max / sum-of-exp / diagonal score survive.
#define TI 32
#define TJ 128
#define WN 159          // Wp window rows per tile = TI + TJ - 1
// smem layout (floats): Qt[64][36] | Kt[64][132] | Wt[64][164] | wb[160] | sdiag[32]
#define OFF_KT   (64*36)
#define OFF_WT   (OFF_KT + 64*132)
#define OFF_WB   (OFF_WT + 64*164)
#define OFF_SD   (OFF_WB + 160)
#define SMEM_FLOATS (OFF_SD + 32)

__global__ __launch_bounds__(256)
void attn_diag_kernel(const float* __restrict__ Wp, const float* __restrict__ Wpb)
{
    extern __shared__ float sm[];
    float (*Qt)[36]  = (float(*)[36]) sm;
    float (*Kt)[132] = (float(*)[132])(sm + OFF_KT);
    float (*Wt)[164] = (float(*)[164])(sm + OFF_WT);
    float* wb    = sm + OFF_WB;
    float* sdiag = sm + OFF_SD;

    int bh = blockIdx.y;                 // 0..31  (b*8+h)
    int i0 = blockIdx.x * TI;
    const float* Qh = g_Q + (size_t)bh * L_ * D_;
    const float* Kh = g_K + (size_t)bh * L_ * D_;

    int tid = threadIdx.x;
    int tx = tid & 15, ty = tid >> 4;

    // load Q tile transposed: Qt[d][i-i0]
    for (int t = tid; t < TI*16; t += 256) {
        int r = t >> 4, c4 = (t & 15) * 4;
        float4 v = *(const float4*)&Qh[(size_t)(i0 + r) * D_ + c4];
        Qt[c4+0][r] = v.x; Qt[c4+1][r] = v.y; Qt[c4+2][r] = v.z; Qt[c4+3][r] = v.w;
    }

    float rm0 = -3.0e38f, rm1 = -3.0e38f;   // running max per row
    float rs0 = 0.f,      rs1 = 0.f;        // running sum per row

    const int i_g0 = i0 + ty*2;
    const int i_g1 = i_g0 + 1;
    const int c1 = tx - 2*ty + 30;          // Wt col for row i_g1, jj=0

    for (int jt = 0; jt < L_/TJ; jt++) {
        int j0 = jt * TJ;
        int rbase = j0 - i0 - (TI - 1) + (L_ - 1);   // always in [0, 4095-WN]
        __syncthreads();
        // load K tile transposed: Kt[d][j-j0]
        for (int t = tid; t < TJ*16; t += 256) {
            int r = t >> 4, c4 = (t & 15) * 4;
            float4 v = *(const float4*)&Kh[(size_t)(j0 + r) * D_ + c4];
            Kt[c4+0][r] = v.x; Kt[c4+1][r] = v.y; Kt[c4+2][r] = v.z; Kt[c4+3][r] = v.w;
        }
        // load Wp window transposed: Wt[d][r-rbase]
        for (int t = tid; t < WN*16; t += 256) {
            int r = t >> 4, c4 = (t & 15) * 4;
            float4 v = *(const float4*)&Wp[(size_t)(rbase + r) * D_ + c4];
            Wt[c4+0][r] = v.x; Wt[c4+1][r] = v.y; Wt[c4+2][r] = v.z; Wt[c4+3][r] = v.w;
        }
        for (int t = tid; t < WN; t += 256) wb[t] = Wpb[rbase + t];
        __syncthreads();

        // each thread: rows (i_g0,i_g1), cols j = j0 + tx + 16*jj  (strided -> conflict-free LDS)
        float ak0[8] = {}, ak1[8] = {}, aw0[8] = {}, aw1[8] = {};
        #pragma unroll 4
        for (int d = 0; d < D_; d++) {
            float q0 = Qt[d][ty*2];
            float q1 = Qt[d][ty*2 + 1];
            #pragma unroll
            for (int jj = 0; jj < 8; jj++) {
                float kv = Kt[d][tx + jj*16];
                float w1 = Wt[d][c1     + jj*16];   // row i_g1
                float w0 = Wt[d][c1 + 1 + jj*16];   // row i_g0
                ak0[jj] += q0 * kv;
                ak1[jj] += q1 * kv;
                aw0[jj] += q0 * w0;
                aw1[jj] += q1 * w1;
            }
        }

        float s0[8], s1[8];
        #pragma unroll
        for (int jj = 0; jj < 8; jj++) {
            s0[jj] = ak0[jj] + aw0[jj] + wb[c1 + 1 + jj*16];
            s1[jj] = ak1[jj] + aw1[jj] + wb[c1     + jj*16];
        }

        // capture diagonal (unnormalized score)
        #pragma unroll
        for (int jj = 0; jj < 8; jj++) {
            int j = j0 + tx + jj*16;
            if (j == i_g0) sdiag[ty*2]     = s0[jj];
            if (j == i_g1) sdiag[ty*2 + 1] = s1[jj];
        }

        // tile max per row, reduced over the 16 tx lanes
        float t0 = s0[0], t1 = s1[0];
        #pragma unroll
        for (int jj = 1; jj < 8; jj++) { t0 = fmaxf(t0, s0[jj]); t1 = fmaxf(t1, s1[jj]); }
        #pragma unroll
        for (int off = 8; off; off >>= 1) {
            t0 = fmaxf(t0, __shfl_xor_sync(0xffffffffu, t0, off));
            t1 = fmaxf(t1, __shfl_xor_sync(0xffffffffu, t1, off));
        }
        float nm0 = fmaxf(rm0, t0), nm1 = fmaxf(rm1, t1);
        float e0 = 0.f, e1 = 0.f;
        #pragma unroll
        for (int jj = 0; jj < 8; jj++) {
            e0 += __expf(s0[jj] - nm0);
            e1 += __expf(s1[jj] - nm1);
        }
        #pragma unroll
        for (int off = 8; off; off >>= 1) {
            e0 += __shfl_xor_sync(0xffffffffu, e0, off);
            e1 += __shfl_xor_sync(0xffffffffu, e1, off);
        }
        rs0 = rs0 * __expf(rm0 - nm0) + e0;
        rs1 = rs1 * __expf(rm1 - nm1) + e1;
        rm0 = nm0; rm1 = nm1;
    }

    __syncthreads();
    if (tx == 0) {
        g_Diag[(size_t)bh * L_ + i_g0] = __expf(sdiag[ty*2]     - rm0) / rs0;
        g_Diag[(size_t)bh * L_ + i_g1] = __expf(sdiag[ty*2 + 1] - rm1) / rs1;
    }
}

// ---------------- Kernel 3: out_pre = diag * v, scatter to (b,l,h*64+d) --------
__global__ __launch_bounds__(256)
void scale_v_kernel()
{
    int idx = blockIdx.x * blockDim.x + threadIdx.x;   // 0 .. 1048575 (float4 units)
    int d4 = idx & 15;
    int i  = (idx >> 4) & (L_ - 1);
    int bh = idx >> 15;
    float dg = g_Diag[(size_t)bh * L_ + i];
    float4 v = ((const float4*)g_V)[idx];
    float4 o; o.x = v.x*dg; o.y = v.y*dg; o.z = v.z*dg; o.w = v.w*dg;
    int b = bh >> 3, h = bh & 7;
    ((float4*)g_Opre)[((size_t)(b * L_ + i)) * 128 + h * 16 + d4] = o;
}

// ---------------- Kernel 4: final projection, writes d_out ----------------------
__global__ __launch_bounds__(256)
void gemm_out_kernel(const float* __restrict__ Wo, const float* __restrict__ bo,
                     float* __restrict__ out)
{
    __shared__ float As[16][68];
    __shared__ float Bs[16][68];

    int tid = threadIdx.x;
    int tx = tid & 15, ty = tid >> 4;
    int m0 = blockIdx.y * 64;
    int n0 = blockIdx.x * 64;

    int lr = tid >> 2;
    int lc = (tid & 3) * 4;

    float acc[4][4] = {};

    for (int k0 = 0; k0 < H_; k0 += 16) {
        float4 av = *(const float4*)&g_Opre[(size_t)(m0 + lr) * H_ + k0 + lc];
        float4 wv = *(const float4*)&Wo[(size_t)(n0 + lr) * H_ + k0 + lc];
        As[lc+0][lr] = av.x; As[lc+1][lr] = av.y; As[lc+2][lr] = av.z; As[lc+3][lr] = av.w;
        Bs[lc+0][lr] = wv.x; Bs[lc+1][lr] = wv.y; Bs[lc+2][lr] = wv.z; Bs[lc+3][lr] = wv.w;
        __syncthreads();
        #pragma unroll
        for (int kk = 0; kk < 16; kk++) {
            float4 a = *(const float4*)&As[kk][ty*4];
            float4 b = *(const float4*)&Bs[kk][tx*4];
            float ar[4] = {a.x, a.y, a.z, a.w};
            float br[4] = {b.x, b.y, b.z, b.w};
            #pragma unroll
            for (int i = 0; i < 4; i++)
                #pragma unroll
                for (int j = 0; j < 4; j++) acc[i][j] += ar[i] * br[j];
        }
        __syncthreads();
    }

    #pragma unroll
    for (int i = 0; i < 4; i++) {
        int row = m0 + ty*4 + i;
        #pragma unroll
        for (int j = 0; j < 4; j++) {
            int n = n0 + tx*4 + j;
            out[(size_t)row * H_ + n] = acc[i][j] + bo[n];
        }
    }
}

// ---------------- launch --------------------------------------------------------
extern "C" void kernel_launch(void* const* d_in, const int* in_sizes, int n_in,
                              void* d_out, int out_size)
{
    const float* q_in = (const float*)d_in[0];
    const float* k_in = (const float*)d_in[1];
    const float* v_in = (const float*)d_in[2];
    const float* Wq_w = (const float*)d_in[3];
    const float* Wq_b = (const float*)d_in[4];
    const float* Wk_w = (const float*)d_in[5];
    const float* Wk_b = (const float*)d_in[6];
    const float* Wv_w = (const float*)d_in[7];
    const float* Wv_b = (const float*)d_in[8];
    const float* Wo_w = (const float*)d_in[9];
    const float* Wo_b = (const float*)d_in[10];
    const float* Wp_w = (const float*)d_in[11];
    const float* Wp_b = (const float*)d_in[12];

    const int smem_bytes = SMEM_FLOATS * (int)sizeof(float);   // ~85.8 KB
    cudaFuncSetAttribute(attn_diag_kernel,
                         cudaFuncAttributeMaxDynamicSharedMemorySize, smem_bytes);

    gemm_qkv_kernel<<<dim3(H_/64, (B_*L_)/64, 3), 256>>>(
        q_in, k_in, v_in, Wq_w, Wq_b, Wk_w, Wk_b, Wv_w, Wv_b);

    attn_diag_kernel<<<dim3(L_/TI, B_*NH), 256, smem_bytes>>>(Wp_w, Wp_b);

    scale_v_kernel<<<(B_*NH*L_*D_/4) / 256, 256>>>();

    gemm_out_kernel<<<dim3(H_/64, (B_*L_)/64), 256>>>(Wo_w, Wo_b, (float*)d_out);
}

// round 2
// speedup vs baseline: 1.0021x; 1.0021x over previous
#include <cuda_runtime.h>
#include <cstdint>

#define B_  4
#define L_  2048
#define H_  512
#define NH  8
#define D_  64

// ---------------- scratch (static device globals; no allocation) ----------------
__device__ float g_Q[B_*NH*L_*D_];      // 16 MB, head layout (b,h,l,d), pre-scaled
__device__ float g_K[B_*NH*L_*D_];      // 16 MB
__device__ float g_V[B_*NH*L_*D_];      // 16 MB
__device__ float g_Diag[B_*NH*L_];      // softmax diagonal values
__device__ float g_Opre[B_*L_*H_];      // 16 MB, (b,l,h*64+d) = diag * v

// ---------------- Kernel 1: fused QKV projection GEMMs --------------------------
// C = A(M,K) @ W(N,K)^T + bias, written into head layout. M=8192,N=512,K=512.
// 64x64 tile, BK=16, 256 threads, 4x4 microtile.
__global__ __launch_bounds__(256)
void gemm_qkv_kernel(const float* __restrict__ q_in, const float* __restrict__ k_in,
                     const float* __restrict__ v_in,
                     const float* __restrict__ Wq, const float* __restrict__ bq,
                     const float* __restrict__ Wk, const float* __restrict__ bk,
                     const float* __restrict__ Wv, const float* __restrict__ bv)
{
    const float* A; const float* W; const float* bias; float* Cout; float scale;
    int mode = blockIdx.z;
    if (mode == 0)      { A = q_in; W = Wq; bias = bq; Cout = g_Q; scale = 0.125f; }
    else if (mode == 1) { A = k_in; W = Wk; bias = bk; Cout = g_K; scale = 1.0f;   }
    else                { A = v_in; W = Wv; bias = bv; Cout = g_V; scale = 1.0f;   }

    __shared__ float As[16][68];
    __shared__ float Bs[16][68];

    int tid = threadIdx.x;
    int tx = tid & 15, ty = tid >> 4;
    int m0 = blockIdx.y * 64;
    int n0 = blockIdx.x * 64;

    int lr = tid >> 2;          // 0..63
    int lc = (tid & 3) * 4;     // 0,4,8,12

    float acc[4][4] = {};

    for (int k0 = 0; k0 < H_; k0 += 16) {
        float4 av = *(const float4*)&A[(size_t)(m0 + lr) * H_ + k0 + lc];
        float4 wv = *(const float4*)&W[(size_t)(n0 + lr) * H_ + k0 + lc];
        As[lc+0][lr] = av.x; As[lc+1][lr] = av.y; As[lc+2][lr] = av.z; As[lc+3][lr] = av.w;
        Bs[lc+0][lr] = wv.x; Bs[lc+1][lr] = wv.y; Bs[lc+2][lr] = wv.z; Bs[lc+3][lr] = wv.w;
        __syncthreads();
        #pragma unroll
        for (int kk = 0; kk < 16; kk++) {
            float4 a = *(const float4*)&As[kk][ty*4];
            float4 b = *(const float4*)&Bs[kk][tx*4];
            float ar[4] = {a.x, a.y, a.z, a.w};
            float br[4] = {b.x, b.y, b.z, b.w};
            #pragma unroll
            for (int i = 0; i < 4; i++)
                #pragma unroll
                for (int j = 0; j < 4; j++) acc[i][j] += ar[i] * br[j];
        }
        __syncthreads();
    }

    #pragma unroll
    for (int i = 0; i < 4; i++) {
        int row = m0 + ty*4 + i;
        int b   = row >> 11;          // /2048
        int ii  = row & (L_ - 1);
        #pragma unroll
        for (int j = 0; j < 4; j++) {
            int n = n0 + tx*4 + j;
            int h = n >> 6, d = n & 63;
            Cout[(((size_t)(b*NH + h) * L_ + ii) * D_) + d] = (acc[i][j] + bias[n]) * scale;
        }
    }
}

// ---------------- Kernel 2: fused scores + relative-pos + online-softmax diag ---
// Block: 32 query rows (one head). Loop over 128-wide j tiles.
// s[i,j] = q_i.k_j + q_i.Wp[j-i+2047] + Wp_b[j-i+2047]
// Only row max / sum-of-exp / diagonal score survive.
#define TI 32
#define TJ 128
#define WN 159          // Wp window rows per tile = TI + TJ - 1
// smem layout (floats): Qt[64][36] | Kt[64][132] | Wt[64][164] | wb[160] | sdiag[32]
#define OFF_KT   (64*36)
#define OFF_WT   (OFF_KT + 64*132)
#define OFF_WB   (OFF_WT + 64*164)
#define OFF_SD   (OFF_WB + 160)
#define SMEM_FLOATS (OFF_SD + 32)

__global__ __launch_bounds__(256)
void attn_diag_kernel(const float* __restrict__ Wp, const float* __restrict__ Wpb)
{
    extern __shared__ float sm[];
    float (*Qt)[36]  = (float(*)[36]) sm;
    float (*Kt)[132] = (float(*)[132])(sm + OFF_KT);
    float (*Wt)[164] = (float(*)[164])(sm + OFF_WT);
    float* wb    = sm + OFF_WB;
    float* sdiag = sm + OFF_SD;

    int bh = blockIdx.y;                 // 0..31  (b*8+h)
    int i0 = blockIdx.x * TI;
    const float* Qh = g_Q + (size_t)bh * L_ * D_;
    const float* Kh = g_K + (size_t)bh * L_ * D_;

    int tid = threadIdx.x;
    int tx = tid & 15, ty = tid >> 4;

    // load Q tile transposed: Qt[d][i-i0]
    for (int t = tid; t < TI*16; t += 256) {
        int r = t >> 4, c4 = (t & 15) * 4;
        float4 v = *(const float4*)&Qh[(size_t)(i0 + r) * D_ + c4];
        Qt[c4+0][r] = v.x; Qt[c4+1][r] = v.y; Qt[c4+2][r] = v.z; Qt[c4+3][r] = v.w;
    }

    float rm0 = -3.0e38f, rm1 = -3.0e38f;   // running max per row
    float rs0 = 0.f,      rs1 = 0.f;        // running sum per row

    const int i_g0 = i0 + ty*2;
    const int i_g1 = i_g0 + 1;
    const int c1 = tx - 2*ty + 30;          // Wt col for row i_g1, jj=0

    for (int jt = 0; jt < L_/TJ; jt++) {
        int j0 = jt * TJ;
        int rbase = j0 - i0 - (TI - 1) + (L_ - 1);   // always in [0, 4095-WN]
        __syncthreads();
        // load K tile transposed: Kt[d][j-j0]
        for (int t = tid; t < TJ*16; t += 256) {
            int r = t >> 4, c4 = (t & 15) * 4;
            float4 v = *(const float4*)&Kh[(size_t)(j0 + r) * D_ + c4];
            Kt[c4+0][r] = v.x; Kt[c4+1][r] = v.y; Kt[c4+2][r] = v.z; Kt[c4+3][r] = v.w;
        }
        // load Wp window transposed: Wt[d][r-rbase]
        for (int t = tid; t < WN*16; t += 256) {
            int r = t >> 4, c4 = (t & 15) * 4;
            float4 v = *(const float4*)&Wp[(size_t)(rbase + r) * D_ + c4];
            Wt[c4+0][r] = v.x; Wt[c4+1][r] = v.y; Wt[c4+2][r] = v.z; Wt[c4+3][r] = v.w;
        }
        for (int t = tid; t < WN; t += 256) wb[t] = Wpb[rbase + t];
        __syncthreads();

        // each thread: rows (i_g0,i_g1), cols j = j0 + tx + 16*jj  (strided -> conflict-free LDS)
        float ak0[8] = {}, ak1[8] = {}, aw0[8] = {}, aw1[8] = {};
        #pragma unroll 4
        for (int d = 0; d < D_; d++) {
            float q0 = Qt[d][ty*2];
            float q1 = Qt[d][ty*2 + 1];
            #pragma unroll
            for (int jj = 0; jj < 8; jj++) {
                float kv = Kt[d][tx + jj*16];
                float w1 = Wt[d][c1     + jj*16];   // row i_g1
                float w0 = Wt[d][c1 + 1 + jj*16];   // row i_g0
                ak0[jj] += q0 * kv;
                ak1[jj] += q1 * kv;
                aw0[jj] += q0 * w0;
                aw1[jj] += q1 * w1;
            }
        }

        float s0[8], s1[8];
        #pragma unroll
        for (int jj = 0; jj < 8; jj++) {
            s0[jj] = ak0[jj] + aw0[jj] + wb[c1 + 1 + jj*16];
            s1[jj] = ak1[jj] + aw1[jj] + wb[c1     + jj*16];
        }

        // capture diagonal (unnormalized score)
        #pragma unroll
        for (int jj = 0; jj < 8; jj++) {
            int j = j0 + tx + jj*16;
            if (j == i_g0) sdiag[ty*2]     = s0[jj];
            if (j == i_g1) sdiag[ty*2 + 1] = s1[jj];
        }

        // tile max per row, reduced over the 16 tx lanes
        float t0 = s0[0], t1 = s1[0];
        #pragma unroll
        for (int jj = 1; jj < 8; jj++) { t0 = fmaxf(t0, s0[jj]); t1 = fmaxf(t1, s1[jj]); }
        #pragma unroll
        for (int off = 8; off; off >>= 1) {
            t0 = fmaxf(t0, __shfl_xor_sync(0xffffffffu, t0, off));
            t1 = fmaxf(t1, __shfl_xor_sync(0xffffffffu, t1, off));
        }
        float nm0 = fmaxf(rm0, t0), nm1 = fmaxf(rm1, t1);
        float e0 = 0.f, e1 = 0.f;
        #pragma unroll
        for (int jj = 0; jj < 8; jj++) {
            e0 += __expf(s0[jj] - nm0);
            e1 += __expf(s1[jj] - nm1);
        }
        #pragma unroll
        for (int off = 8; off; off >>= 1) {
            e0 += __shfl_xor_sync(0xffffffffu, e0, off);
            e1 += __shfl_xor_sync(0xffffffffu, e1, off);
        }
        rs0 = rs0 * __expf(rm0 - nm0) + e0;
        rs1 = rs1 * __expf(rm1 - nm1) + e1;
        rm0 = nm0; rm1 = nm1;
    }

    __syncthreads();
    if (tx == 0) {
        g_Diag[(size_t)bh * L_ + i_g0] = __expf(sdiag[ty*2]     - rm0) / rs0;
        g_Diag[(size_t)bh * L_ + i_g1] = __expf(sdiag[ty*2 + 1] - rm1) / rs1;
    }
}

// ---------------- Kernel 3: out_pre = diag * v, scatter to (b,l,h*64+d) --------
__global__ __launch_bounds__(256)
void scale_v_kernel()
{
    int idx = blockIdx.x * blockDim.x + threadIdx.x;   // 0 .. 1048575 (float4 units)
    int d4 = idx & 15;
    int i  = (idx >> 4) & (L_ - 1);
    int bh = idx >> 15;
    float dg = g_Diag[(size_t)bh * L_ + i];
    float4 v = ((const float4*)g_V)[idx];
    float4 o; o.x = v.x*dg; o.y = v.y*dg; o.z = v.z*dg; o.w = v.w*dg;
    int b = bh >> 3, h = bh & 7;
    ((float4*)g_Opre)[((size_t)(b * L_ + i)) * 128 + h * 16 + d4] = o;
}

// ---------------- Kernel 4: final projection, writes d_out ----------------------
__global__ __launch_bounds__(256)
void gemm_out_kernel(const float* __restrict__ Wo, const float* __restrict__ bo,
                     float* __restrict__ out)
{
    __shared__ float As[16][68];
    __shared__ float Bs[16][68];

    int tid = threadIdx.x;
    int tx = tid & 15, ty = tid >> 4;
    int m0 = blockIdx.y * 64;
    int n0 = blockIdx.x * 64;

    int lr = tid >> 2;
    int lc = (tid & 3) * 4;

    float acc[4][4] = {};

    for (int k0 = 0; k0 < H_; k0 += 16) {
        float4 av = *(const float4*)&g_Opre[(size_t)(m0 + lr) * H_ + k0 + lc];
        float4 wv = *(const float4*)&Wo[(size_t)(n0 + lr) * H_ + k0 + lc];
        As[lc+0][lr] = av.x; As[lc+1][lr] = av.y; As[lc+2][lr] = av.z; As[lc+3][lr] = av.w;
        Bs[lc+0][lr] = wv.x; Bs[lc+1][lr] = wv.y; Bs[lc+2][lr] = wv.z; Bs[lc+3][lr] = wv.w;
        __syncthreads();
        #pragma unroll
        for (int kk = 0; kk < 16; kk++) {
            float4 a = *(const float4*)&As[kk][ty*4];
            float4 b = *(const float4*)&Bs[kk][tx*4];
            float ar[4] = {a.x, a.y, a.z, a.w};
            float br[4] = {b.x, b.y, b.z, b.w};
            #pragma unroll
            for (int i = 0; i < 4; i++)
                #pragma unroll
                for (int j = 0; j < 4; j++) acc[i][j] += ar[i] * br[j];
        }
        __syncthreads();
    }

    #pragma unroll
    for (int i = 0; i < 4; i++) {
        int row = m0 + ty*4 + i;
        #pragma unroll
        for (int j = 0; j < 4; j++) {
            int n = n0 + tx*4 + j;
            out[(size_t)row * H_ + n] = acc[i][j] + bo[n];
        }
    }
}

// ---------------- launch --------------------------------------------------------
extern "C" void kernel_launch(void* const* d_in, const int* in_sizes, int n_in,
                              void* d_out, int out_size)
{
    const float* q_in = (const float*)d_in[0];
    const float* k_in = (const float*)d_in[1];
    const float* v_in = (const float*)d_in[2];
    const float* Wq_w = (const float*)d_in[3];
    const float* Wq_b = (const float*)d_in[4];
    const float* Wk_w = (const float*)d_in[5];
    const float* Wk_b = (const float*)d_in[6];
    const float* Wv_w = (const float*)d_in[7];
    const float* Wv_b = (const float*)d_in[8];
    const float* Wo_w = (const float*)d_in[9];
    const float* Wo_b = (const float*)d_in[10];
    const float* Wp_w = (const float*)d_in[11];
    const float* Wp_b = (const float*)d_in[12];

    const int smem_bytes = SMEM_FLOATS * (int)sizeof(float);   // ~85.8 KB
    cudaFuncSetAttribute(attn_diag_kernel,
                         cudaFuncAttributeMaxDynamicSharedMemorySize, smem_bytes);

    gemm_qkv_kernel<<<dim3(H_/64, (B_*L_)/64, 3), 256>>>(
        q_in, k_in, v_in, Wq_w, Wq_b, Wk_w, Wk_b, Wv_w, Wv_b);

    attn_diag_kernel<<<dim3(L_/TI, B_*NH), 256, smem_bytes>>>(Wp_w, Wp_b);

    scale_v_kernel<<<(B_*NH*L_*D_/4) / 256, 256>>>();

    gemm_out_kernel<<<dim3(H_/64, (B_*L_)/64), 256>>>(Wo_w, Wo_b, (float*)d_out);
}

// round 4
// speedup vs baseline: 2.7568x; 2.7511x over previous
#include <cuda_runtime.h>
#include <cuda_bf16.h>
#include <cstdint>

#define B_  4
#define L_  2048
#define H_  512
#define NH  8
#define D_  64

// ---------------- scratch (static device globals; no allocation) ----------------
__device__ __nv_bfloat16 g_Qbf[B_*NH*L_*D_];   // 8 MB, (b,h,l,d), scaled by 0.125*log2e
__device__ __nv_bfloat16 g_Kbf[B_*NH*L_*D_];   // 8 MB
__device__ __nv_bfloat16 g_Wpbf[4096*D_];      // 512 KB, rows >= 4095 zero-padded
__device__ float g_V[B_*NH*L_*D_];             // 16 MB
__device__ float g_Diag[B_*NH*L_];             // softmax diagonal values
__device__ float g_Opre[B_*L_*H_];             // 16 MB, (b,l,h*64+d) = diag * v

__device__ __forceinline__ float fast_exp2(float x) {
    float y; asm("ex2.approx.f32 %0, %1;" : "=f"(y) : "f"(x)); return y;
}
__device__ __forceinline__ void mma16816(float* c, uint32_t a0, uint32_t a1,
                                         uint32_t a2, uint32_t a3,
                                         uint32_t b0, uint32_t b1) {
    asm volatile(
        "mma.sync.aligned.m16n8k16.row.col.f32.bf16.bf16.f32 "
        "{%0,%1,%2,%3}, {%4,%5,%6,%7}, {%8,%9}, {%0,%1,%2,%3};"
        : "+f"(c[0]), "+f"(c[1]), "+f"(c[2]), "+f"(c[3])
        : "r"(a0), "r"(a1), "r"(a2), "r"(a3), "r"(b0), "r"(b1));
}

// ---------------- Kernel 1: fused QKV projection GEMMs --------------------------
__global__ __launch_bounds__(256)
void gemm_qkv_kernel(const float* __restrict__ q_in, const float* __restrict__ k_in,
                     const float* __restrict__ v_in,
                     const float* __restrict__ Wq, const float* __restrict__ bq,
                     const float* __restrict__ Wk, const float* __restrict__ bk,
                     const float* __restrict__ Wv, const float* __restrict__ bv)
{
    const float* A; const float* W; const float* bias;
    int mode = blockIdx.z;
    if (mode == 0)      { A = q_in; W = Wq; bias = bq; }
    else if (mode == 1) { A = k_in; W = Wk; bias = bk; }
    else                { A = v_in; W = Wv; bias = bv; }

    __shared__ float As[16][68];
    __shared__ float Bs[16][68];

    int tid = threadIdx.x;
    int tx = tid & 15, ty = tid >> 4;
    int m0 = blockIdx.y * 64;
    int n0 = blockIdx.x * 64;

    int lr = tid >> 2;
    int lc = (tid & 3) * 4;

    float acc[4][4] = {};

    for (int k0 = 0; k0 < H_; k0 += 16) {
        float4 av = *(const float4*)&A[(size_t)(m0 + lr) * H_ + k0 + lc];
        float4 wv = *(const float4*)&W[(size_t)(n0 + lr) * H_ + k0 + lc];
        As[lc+0][lr] = av.x; As[lc+1][lr] = av.y; As[lc+2][lr] = av.z; As[lc+3][lr] = av.w;
        Bs[lc+0][lr] = wv.x; Bs[lc+1][lr] = wv.y; Bs[lc+2][lr] = wv.z; Bs[lc+3][lr] = wv.w;
        __syncthreads();
        #pragma unroll
        for (int kk = 0; kk < 16; kk++) {
            float4 a = *(const float4*)&As[kk][ty*4];
            float4 b = *(const float4*)&Bs[kk][tx*4];
            float ar[4] = {a.x, a.y, a.z, a.w};
            float br[4] = {b.x, b.y, b.z, b.w};
            #pragma unroll
            for (int i = 0; i < 4; i++)
                #pragma unroll
                for (int j = 0; j < 4; j++) acc[i][j] += ar[i] * br[j];
        }
        __syncthreads();
    }

    const float qscale = 0.125f * 1.4426950408889634f;  // fold log2e into Q
    #pragma unroll
    for (int i = 0; i < 4; i++) {
        int row = m0 + ty*4 + i;
        int b   = row >> 11;
        int ii  = row & (L_ - 1);
        #pragma unroll
        for (int j = 0; j < 4; j++) {
            int n = n0 + tx*4 + j;
            int h = n >> 6, d = n & 63;
            size_t idx = (((size_t)(b*NH + h) * L_ + ii) * D_) + d;
            float v = acc[i][j] + bias[n];
            if (mode == 0)      g_Qbf[idx] = __float2bfloat16(v * qscale);
            else if (mode == 1) g_Kbf[idx] = __float2bfloat16(v);
            else                g_V[idx] = v;
        }
    }
}

// ---------------- Kernel 1b: convert Wp to padded bf16 --------------------------
__global__ __launch_bounds__(256)
void wp_convert_kernel(const float* __restrict__ Wp)
{
    int idx = blockIdx.x * 256 + threadIdx.x;   // < 4096*64
    int r = idx >> 6;
    g_Wpbf[idx] = __float2bfloat16(r < 2*L_ - 1 ? Wp[idx] : 0.f);
}

// ---------------- Kernel 2: HMMA score pass + softmax diagonal ------------------
// i-tile 128 rows x one head. Per 128-col j-tile:
//   S = Q.K^T (128x128), P = Q.Wpwin^T (128x256) via mma.sync bf16.
//   skew: s[row][jj] = S[row][jj] + P[row][jj-row+127] + bias  (gather via pitch-258 smem)
#define ATI 128
#define QPITCH 72          // bf16 elements per smem row (conflict-free frag loads)
#define PPITCH 258
// byte offsets into dynamic smem
#define OFF_QS 0
#define OFF_KS 18432
#define OFF_WS 36864                       // 256 rows
#define OFF_PS 73728                       // 128*258 floats
#define OFF_WB 205824                      // 256 floats
#define OFF_SD 206848                      // 128 floats
#define OFF_RED 207360                     // 256 floats
#define ATT_SMEM 208384

__global__ __launch_bounds__(256, 1)
void attn_mma_kernel(const float* __restrict__ Wpb)
{
    extern __shared__ char smc[];
    __nv_bfloat16* Qs = (__nv_bfloat16*)(smc + OFF_QS);
    __nv_bfloat16* Ks = (__nv_bfloat16*)(smc + OFF_KS);
    __nv_bfloat16* Ws = (__nv_bfloat16*)(smc + OFF_WS);
    float* Psm   = (float*)(smc + OFF_PS);
    float* wb    = (float*)(smc + OFF_WB);
    float* sdArr = (float*)(smc + OFF_SD);
    float* red   = (float*)(smc + OFF_RED);

    int tid = threadIdx.x;
    int lane = tid & 31, w = tid >> 5;
    int wr = w >> 1, wc = w & 1;          // warp row (4), warp col (2)
    int g = lane >> 2, qd = lane & 3;     // mma group / quad lane
    int bh = blockIdx.y;
    int it = blockIdx.x;
    int i0 = it * ATI;

    // load Q tile (128 x 64 bf16 -> pitch-72 smem)
    {
        const uint4* Qg4 = (const uint4*)(g_Qbf + ((size_t)bh * L_ + i0) * D_);
        for (int t = tid; t < 1024; t += 256) {
            int r = t >> 3, c = t & 7;
            *(uint4*)(Qs + r*QPITCH + c*8) = Qg4[t];
        }
    }

    float rs[4] = {0.f, 0.f, 0.f, 0.f};   // per-thread row sums: [mf*2 + (0:g,1:g+8)]

    for (int jt = 0; jt < L_/ATI; jt++) {
        int j0 = jt * ATI;
        int rbase = j0 - i0 + (L_ - ATI);  // in [0, 3840]
        __syncthreads();                   // prev epilogue done -> reuse smem

        // K tile (128 x 64)
        const uint4* Kg4 = (const uint4*)(g_Kbf + ((size_t)bh * L_ + j0) * D_);
        for (int t = tid; t < 1024; t += 256) {
            int r = t >> 3, c = t & 7;
            *(uint4*)(Ks + r*QPITCH + c*8) = Kg4[t];
        }
        // Wp window (256 x 64)
        const uint4* Wg4 = (const uint4*)(g_Wpbf + (size_t)rbase * D_);
        for (int t = tid; t < 2048; t += 256) {
            int r = t >> 3, c = t & 7;
            *(uint4*)(Ws + r*QPITCH + c*8) = Wg4[t];
        }
        // bias window (x log2e); col 255 never gathered
        wb[tid] = (tid < 255) ? Wpb[rbase + tid] * 1.4426950408889634f : 0.f;
        __syncthreads();

        // ---- P = Q . Wwin^T, two 64-col halves per warp; store to Psm (+bias)
        #pragma unroll
        for (int h = 0; h < 2; h++) {
            float accP[2][8][4] = {};
            #pragma unroll
            for (int kk = 0; kk < 4; kk++) {
                uint32_t a[2][4];
                #pragma unroll
                for (int mf = 0; mf < 2; mf++) {
                    const __nv_bfloat16* qp = Qs + (wr*32 + mf*16 + g)*QPITCH + kk*16 + qd*2;
                    a[mf][0] = *(const uint32_t*)(qp);
                    a[mf][1] = *(const uint32_t*)(qp + 8*QPITCH);
                    a[mf][2] = *(const uint32_t*)(qp + 8);
                    a[mf][3] = *(const uint32_t*)(qp + 8*QPITCH + 8);
                }
                #pragma unroll
                for (int nf = 0; nf < 8; nf++) {
                    const __nv_bfloat16* bp = Ws + (wc*128 + h*64 + nf*8 + g)*QPITCH + kk*16 + qd*2;
                    uint32_t b0 = *(const uint32_t*)(bp);
                    uint32_t b1 = *(const uint32_t*)(bp + 8);
                    mma16816(accP[0][nf], a[0][0], a[0][1], a[0][2], a[0][3], b0, b1);
                    mma16816(accP[1][nf], a[1][0], a[1][1], a[1][2], a[1][3], b0, b1);
                }
            }
            #pragma unroll
            for (int mf = 0; mf < 2; mf++)
                #pragma unroll
                for (int nf = 0; nf < 8; nf++) {
                    int row = wr*32 + mf*16 + g;
                    int col = wc*128 + h*64 + nf*8 + qd*2;
                    float w0 = wb[col], w1 = wb[col+1];
                    Psm[row*PPITCH + col + 1]     = accP[mf][nf][0] + w0;
                    Psm[row*PPITCH + col + 2]     = accP[mf][nf][1] + w1;
                    Psm[(row+8)*PPITCH + col + 1] = accP[mf][nf][2] + w0;
                    Psm[(row+8)*PPITCH + col + 2] = accP[mf][nf][3] + w1;
                }
        }

        // ---- S = Q . K^T (each warp: 32 rows x 64 cols)
        float accS[2][8][4] = {};
        #pragma unroll
        for (int kk = 0; kk < 4; kk++) {
            uint32_t a[2][4];
            #pragma unroll
            for (int mf = 0; mf < 2; mf++) {
                const __nv_bfloat16* qp = Qs + (wr*32 + mf*16 + g)*QPITCH + kk*16 + qd*2;
                a[mf][0] = *(const uint32_t*)(qp);
                a[mf][1] = *(const uint32_t*)(qp + 8*QPITCH);
                a[mf][2] = *(const uint32_t*)(qp + 8);
                a[mf][3] = *(const uint32_t*)(qp + 8*QPITCH + 8);
            }
            #pragma unroll
            for (int nf = 0; nf < 8; nf++) {
                const __nv_bfloat16* bp = Ks + (wc*64 + nf*8 + g)*QPITCH + kk*16 + qd*2;
                uint32_t b0 = *(const uint32_t*)(bp);
                uint32_t b1 = *(const uint32_t*)(bp + 8);
                mma16816(accS[0][nf], a[0][0], a[0][1], a[0][2], a[0][3], b0, b1);
                mma16816(accS[1][nf], a[1][0], a[1][1], a[1][2], a[1][3], b0, b1);
            }
        }
        __syncthreads();   // Psm complete

        // ---- epilogue: t = S + P_gather ; rs += 2^t ; capture diagonal
        bool dt = (jt == it);
        #pragma unroll
        for (int mf = 0; mf < 2; mf++)
            #pragma unroll
            for (int nf = 0; nf < 8; nf++) {
                int r0 = wr*32 + mf*16 + g, r1 = r0 + 8;
                int j  = wc*64 + nf*8 + qd*2;
                float t00 = accS[mf][nf][0] + Psm[r0*(PPITCH-1) + j + 128];
                float t01 = accS[mf][nf][1] + Psm[r0*(PPITCH-1) + j + 129];
                float t10 = accS[mf][nf][2] + Psm[r1*(PPITCH-1) + j + 128];
                float t11 = accS[mf][nf][3] + Psm[r1*(PPITCH-1) + j + 129];
                rs[mf*2+0] += fast_exp2(t00) + fast_exp2(t01);
                rs[mf*2+1] += fast_exp2(t10) + fast_exp2(t11);
                if (dt) {
                    if (j == r0)          sdArr[r0] = t00;
                    else if (j + 1 == r0) sdArr[r0] = t01;
                    if (j == r1)          sdArr[r1] = t10;
                    else if (j + 1 == r1) sdArr[r1] = t11;
                }
            }
    }

    // reduce rs across quad lanes (cols within warp), then across wc halves
    #pragma unroll
    for (int k = 0; k < 4; k++) {
        rs[k] += __shfl_xor_sync(0xffffffffu, rs[k], 1);
        rs[k] += __shfl_xor_sync(0xffffffffu, rs[k], 2);
    }
    if (qd == 0) {
        int base = wc*128 + wr*32;
        red[base + g]          = rs[0];
        red[base + g + 8]      = rs[1];
        red[base + 16 + g]     = rs[2];
        red[base + 16 + g + 8] = rs[3];
    }
    __syncthreads();
    if (tid < 128) {
        float r = red[tid] + red[128 + tid];
        g_Diag[(size_t)bh * L_ + i0 + tid] = fast_exp2(sdArr[tid]) / r;
    }
}

// ---------------- Kernel 3: out_pre = diag * v, scatter to (b,l,h*64+d) --------
__global__ __launch_bounds__(256)
void scale_v_kernel()
{
    int idx = blockIdx.x * blockDim.x + threadIdx.x;
    int d4 = idx & 15;
    int i  = (idx >> 4) & (L_ - 1);
    int bh = idx >> 15;
    float dg = g_Diag[(size_t)bh * L_ + i];
    float4 v = ((const float4*)g_V)[idx];
    float4 o; o.x = v.x*dg; o.y = v.y*dg; o.z = v.z*dg; o.w = v.w*dg;
    int b = bh >> 3, h = bh & 7;
    ((float4*)g_Opre)[((size_t)(b * L_ + i)) * 128 + h * 16 + d4] = o;
}

// ---------------- Kernel 4: final projection, writes d_out ----------------------
__global__ __launch_bounds__(256)
void gemm_out_kernel(const float* __restrict__ Wo, const float* __restrict__ bo,
                     float* __restrict__ out)
{
    __shared__ float As[16][68];
    __shared__ float Bs[16][68];

    int tid = threadIdx.x;
    int tx = tid & 15, ty = tid >> 4;
    int m0 = blockIdx.y * 64;
    int n0 = blockIdx.x * 64;

    int lr = tid >> 2;
    int lc = (tid & 3) * 4;

    float acc[4][4] = {};

    for (int k0 = 0; k0 < H_; k0 += 16) {
        float4 av = *(const float4*)&g_Opre[(size_t)(m0 + lr) * H_ + k0 + lc];
        float4 wv = *(const float4*)&Wo[(size_t)(n0 + lr) * H_ + k0 + lc];
        As[lc+0][lr] = av.x; As[lc+1][lr] = av.y; As[lc+2][lr] = av.z; As[lc+3][lr] = av.w;
        Bs[lc+0][lr] = wv.x; Bs[lc+1][lr] = wv.y; Bs[lc+2][lr] = wv.z; Bs[lc+3][lr] = wv.w;
        __syncthreads();
        #pragma unroll
        for (int kk = 0; kk < 16; kk++) {
            float4 a = *(const float4*)&As[kk][ty*4];
            float4 b = *(const float4*)&Bs[kk][tx*4];
            float ar[4] = {a.x, a.y, a.z, a.w};
            float br[4] = {b.x, b.y, b.z, b.w};
            #pragma unroll
            for (int i = 0; i < 4; i++)
                #pragma unroll
                for (int j = 0; j < 4; j++) acc[i][j] += ar[i] * br[j];
        }
        __syncthreads();
    }

    #pragma unroll
    for (int i = 0; i < 4; i++) {
        int row = m0 + ty*4 + i;
        #pragma unroll
        for (int j = 0; j < 4; j++) {
            int n = n0 + tx*4 + j;
            out[(size_t)row * H_ + n] = acc[i][j] + bo[n];
        }
    }
}

// ---------------- launch --------------------------------------------------------
extern "C" void kernel_launch(void* const* d_in, const int* in_sizes, int n_in,
                              void* d_out, int out_size)
{
    const float* q_in = (const float*)d_in[0];
    const float* k_in = (const float*)d_in[1];
    const float* v_in = (const float*)d_in[2];
    const float* Wq_w = (const float*)d_in[3];
    const float* Wq_b = (const float*)d_in[4];
    const float* Wk_w = (const float*)d_in[5];
    const float* Wk_b = (const float*)d_in[6];
    const float* Wv_w = (const float*)d_in[7];
    const float* Wv_b = (const float*)d_in[8];
    const float* Wo_w = (const float*)d_in[9];
    const float* Wo_b = (const float*)d_in[10];
    const float* Wp_w = (const float*)d_in[11];
    const float* Wp_b = (const float*)d_in[12];

    cudaFuncSetAttribute(attn_mma_kernel,
                         cudaFuncAttributeMaxDynamicSharedMemorySize, ATT_SMEM);

    gemm_qkv_kernel<<<dim3(H_/64, (B_*L_)/64, 3), 256>>>(
        q_in, k_in, v_in, Wq_w, Wq_b, Wk_w, Wk_b, Wv_w, Wv_b);

    wp_convert_kernel<<<(4096*D_)/256, 256>>>(Wp_w);

    attn_mma_kernel<<<dim3(L_/ATI, B_*NH), 256, ATT_SMEM>>>(Wp_b);

    scale_v_kernel<<<(B_*NH*L_*D_/4) / 256, 256>>>();

    gemm_out_kernel<<<dim3(H_/64, (B_*L_)/64), 256>>>(Wo_w, Wo_b, (float*)d_out);
}

// round 5
// speedup vs baseline: 6.1068x; 2.2152x over previous
#include <cuda_runtime.h>
#include <cuda_bf16.h>
#include <cstdint>

#define B_  4
#define L_  2048
#define H_  512
#define NH  8
#define D_  64

// ---------------- scratch (static device globals; no allocation) ----------------
__device__ __nv_bfloat16 g_Qbf[B_*NH*L_*D_];   // (b,h,l,d), scaled by 0.125*log2e
__device__ __nv_bfloat16 g_Kbf[B_*NH*L_*D_];
__device__ __nv_bfloat16 g_Wpbf[4096*D_];      // rows >= 4095 zero-padded
__device__ float g_V[B_*NH*L_*D_];             // fp32 head layout
__device__ float g_Diag[B_*NH*L_];             // softmax diagonal values

__device__ __forceinline__ float fast_exp2(float x) {
    float y; asm("ex2.approx.f32 %0, %1;" : "=f"(y) : "f"(x)); return y;
}
__device__ __forceinline__ void mma16816(float* c, uint32_t a0, uint32_t a1,
                                         uint32_t a2, uint32_t a3,
                                         uint32_t b0, uint32_t b1) {
    asm volatile(
        "mma.sync.aligned.m16n8k16.row.col.f32.bf16.bf16.f32 "
        "{%0,%1,%2,%3}, {%4,%5,%6,%7}, {%8,%9}, {%0,%1,%2,%3};"
        : "+f"(c[0]), "+f"(c[1]), "+f"(c[2]), "+f"(c[3])
        : "r"(a0), "r"(a1), "r"(a2), "r"(a3), "r"(b0), "r"(b1));
}

// ---------------- Kernel 1: QKV projections, bf16 HMMA --------------------------
// C(8192,512) = A(8192,512) @ W(512,512)^T + bias; outputs to head layout.
__global__ __launch_bounds__(256, 2)
void gemm_qkv_bf16(const float* __restrict__ q_in, const float* __restrict__ k_in,
                   const float* __restrict__ v_in,
                   const float* __restrict__ Wq, const float* __restrict__ bq,
                   const float* __restrict__ Wk, const float* __restrict__ bk,
                   const float* __restrict__ Wv, const float* __restrict__ bv)
{
    __shared__ __nv_bfloat16 Ab[128*72];
    __shared__ __nv_bfloat16 Wb[128*72];

    int mode = blockIdx.z;
    const float *A, *W, *bias;
    if (mode == 0)      { A = q_in; W = Wq; bias = bq; }
    else if (mode == 1) { A = k_in; W = Wk; bias = bk; }
    else                { A = v_in; W = Wv; bias = bv; }

    int m0 = blockIdx.y * 128, n0 = blockIdx.x * 128;
    int tid = threadIdx.x, lane = tid & 31, w = tid >> 5;
    int wr = w >> 1, wc = w & 1, g = lane >> 2, qd = lane & 3;
    int rl = tid >> 4, c4 = (tid & 15) * 4;

    float acc[2][8][4] = {};

    for (int k0 = 0; k0 < H_; k0 += 64) {
        __syncthreads();
        #pragma unroll
        for (int i = 0; i < 8; i++) {
            int r = i*16 + rl;
            float4 va = *(const float4*)&A[(size_t)(m0 + r) * H_ + k0 + c4];
            float4 wv = *(const float4*)&W[(size_t)(n0 + r) * H_ + k0 + c4];
            __nv_bfloat162* pa = (__nv_bfloat162*)(Ab + r*72 + c4);
            pa[0] = __halves2bfloat162(__float2bfloat16(va.x), __float2bfloat16(va.y));
            pa[1] = __halves2bfloat162(__float2bfloat16(va.z), __float2bfloat16(va.w));
            __nv_bfloat162* pw = (__nv_bfloat162*)(Wb + r*72 + c4);
            pw[0] = __halves2bfloat162(__float2bfloat16(wv.x), __float2bfloat16(wv.y));
            pw[1] = __halves2bfloat162(__float2bfloat16(wv.z), __float2bfloat16(wv.w));
        }
        __syncthreads();
        #pragma unroll
        for (int kk = 0; kk < 4; kk++) {
            uint32_t a[2][4];
            #pragma unroll
            for (int mf = 0; mf < 2; mf++) {
                const __nv_bfloat16* qp = Ab + (wr*32 + mf*16 + g)*72 + kk*16 + qd*2;
                a[mf][0] = *(const uint32_t*)(qp);
                a[mf][1] = *(const uint32_t*)(qp + 8*72);
                a[mf][2] = *(const uint32_t*)(qp + 8);
                a[mf][3] = *(const uint32_t*)(qp + 8*72 + 8);
            }
            #pragma unroll
            for (int nf = 0; nf < 8; nf++) {
                const __nv_bfloat16* bp = Wb + (wc*64 + nf*8 + g)*72 + kk*16 + qd*2;
                uint32_t b0 = *(const uint32_t*)(bp);
                uint32_t b1 = *(const uint32_t*)(bp + 8);
                mma16816(acc[0][nf], a[0][0],a[0][1],a[0][2],a[0][3], b0,b1);
                mma16816(acc[1][nf], a[1][0],a[1][1],a[1][2],a[1][3], b0,b1);
            }
        }
    }

    const float qs = 0.125f * 1.4426950408889634f;
    #pragma unroll
    for (int mf = 0; mf < 2; mf++) {
        int rg = m0 + wr*32 + mf*16 + g;
        int b = rg >> 11, l = rg & (L_ - 1);
        #pragma unroll
        for (int nf = 0; nf < 8; nf++) {
            int n = n0 + wc*64 + nf*8 + qd*2;
            int h = n >> 6, d = n & 63;
            float b0 = bias[n], b1 = bias[n+1];
            float v00 = acc[mf][nf][0] + b0, v01 = acc[mf][nf][1] + b1;
            float v10 = acc[mf][nf][2] + b0, v11 = acc[mf][nf][3] + b1;
            size_t o0 = ((size_t)(b*NH + h) * L_ + l) * D_ + d;
            size_t o1 = o0 + 8*D_;
            if (mode == 0) {
                *(__nv_bfloat162*)(g_Qbf + o0) =
                    __halves2bfloat162(__float2bfloat16(v00*qs), __float2bfloat16(v01*qs));
                *(__nv_bfloat162*)(g_Qbf + o1) =
                    __halves2bfloat162(__float2bfloat16(v10*qs), __float2bfloat16(v11*qs));
            } else if (mode == 1) {
                *(__nv_bfloat162*)(g_Kbf + o0) =
                    __halves2bfloat162(__float2bfloat16(v00), __float2bfloat16(v01));
                *(__nv_bfloat162*)(g_Kbf + o1) =
                    __halves2bfloat162(__float2bfloat16(v10), __float2bfloat16(v11));
            } else {
                *(float2*)(g_V + o0) = make_float2(v00, v01);
                *(float2*)(g_V + o1) = make_float2(v10, v11);
            }
        }
    }
}

// ---------------- Kernel 1b: convert Wp to padded bf16 --------------------------
__global__ __launch_bounds__(256)
void wp_convert_kernel(const float* __restrict__ Wp)
{
    int idx = blockIdx.x * 256 + threadIdx.x;   // < 4096*64
    int r = idx >> 6;
    g_Wpbf[idx] = __float2bfloat16(r < 2*L_ - 1 ? Wp[idx] : 0.f);
}

// ---------------- Kernel 2: HMMA score pass, rolling-P ring ---------------------
// Per CTA: 128 i-rows x 1 head. Ring position of Wp-row r = 128*((r>>7)%3) + (r&127),
// slot-0 mirrored at cols [384,512) so gather pos = 128*sigma + (j-row+127) never wraps.
#define PSP 520
#define AOFF_KS  18432
#define AOFF_WS  36864
#define AOFF_PS  55296
#define AOFF_WB  188416
#define AOFF_SD  188928
#define AOFF_RED 189440
#define ATT_SMEM 190464

__global__ __launch_bounds__(256, 1)
void attn_mma_kernel(const float* __restrict__ Wpb)
{
    extern __shared__ char smc[];
    __nv_bfloat16* Qs  = (__nv_bfloat16*)(smc);
    __nv_bfloat16* Ks  = (__nv_bfloat16*)(smc + AOFF_KS);
    __nv_bfloat16* Ws  = (__nv_bfloat16*)(smc + AOFF_WS);
    __nv_bfloat16* Psm = (__nv_bfloat16*)(smc + AOFF_PS);
    float* wbn   = (float*)(smc + AOFF_WB);
    float* sdArr = (float*)(smc + AOFF_SD);
    float* red   = (float*)(smc + AOFF_RED);

    const int tid = threadIdx.x;
    const int lane = tid & 31, w = tid >> 5;
    const int wr = w >> 1, wc = w & 1;
    const int g = lane >> 2, qd = lane & 3;
    const int bh = blockIdx.y, it = blockIdx.x;
    const int i0 = it * 128;

    // Q tile (128 x 64 bf16 -> pitch-72 smem)
    {
        const uint4* Qg4 = (const uint4*)(g_Qbf + ((size_t)bh * L_ + i0) * D_);
        for (int t = tid; t < 1024; t += 256) {
            int r = t >> 3, c = t & 7;
            *(uint4*)(Qs + r*72 + c*8) = Qg4[t];
        }
    }

    auto load_block = [&](int base) {
        const uint4* Wg4 = (const uint4*)(g_Wpbf + (size_t)base * D_);
        for (int t = tid; t < 1024; t += 256) {
            int r = t >> 3, c = t & 7;
            *(uint4*)(Ws + r*72 + c*8) = Wg4[t];
        }
        if (tid < 128)
            wbn[tid] = (base + tid < 2*L_ - 1) ? Wpb[base + tid] * 1.4426950408889634f : 0.f;
    };

    // compute 128x128 P block from Ws, store (biased, bf16) into ring slot
    auto pblock = [&](int slot) {
        float accP[2][8][4] = {};
        #pragma unroll
        for (int kk = 0; kk < 4; kk++) {
            uint32_t a[2][4];
            #pragma unroll
            for (int mf = 0; mf < 2; mf++) {
                const __nv_bfloat16* qp = Qs + (wr*32 + mf*16 + g)*72 + kk*16 + qd*2;
                a[mf][0] = *(const uint32_t*)(qp);
                a[mf][1] = *(const uint32_t*)(qp + 8*72);
                a[mf][2] = *(const uint32_t*)(qp + 8);
                a[mf][3] = *(const uint32_t*)(qp + 8*72 + 8);
            }
            #pragma unroll
            for (int nf = 0; nf < 8; nf++) {
                const __nv_bfloat16* bp = Ws + (wc*64 + nf*8 + g)*72 + kk*16 + qd*2;
                uint32_t b0 = *(const uint32_t*)(bp);
                uint32_t b1 = *(const uint32_t*)(bp + 8);
                mma16816(accP[0][nf], a[0][0],a[0][1],a[0][2],a[0][3], b0,b1);
                mma16816(accP[1][nf], a[1][0],a[1][1],a[1][2],a[1][3], b0,b1);
            }
        }
        int pb = slot * 128;
        #pragma unroll
        for (int mf = 0; mf < 2; mf++) {
            int r0 = wr*32 + mf*16 + g, r1 = r0 + 8;
            #pragma unroll
            for (int nf = 0; nf < 8; nf++) {
                int c = wc*64 + nf*8 + qd*2;
                float b0 = wbn[c], b1 = wbn[c+1];
                __nv_bfloat16 v00 = __float2bfloat16(accP[mf][nf][0] + b0);
                __nv_bfloat16 v01 = __float2bfloat16(accP[mf][nf][1] + b1);
                __nv_bfloat16 v10 = __float2bfloat16(accP[mf][nf][2] + b0);
                __nv_bfloat16 v11 = __float2bfloat16(accP[mf][nf][3] + b1);
                Psm[r0*PSP + pb + c]     = v00;
                Psm[r0*PSP + pb + c + 1] = v01;
                Psm[r1*PSP + pb + c]     = v10;
                Psm[r1*PSP + pb + c + 1] = v11;
                if (slot == 0) {   // mirror slot 0 at cols 384..511
                    Psm[r0*PSP + 384 + c]     = v00;
                    Psm[r0*PSP + 384 + c + 1] = v01;
                    Psm[r1*PSP + 384 + c]     = v10;
                    Psm[r1*PSP + 384 + c + 1] = v11;
                }
            }
        }
    };

    const int rbase0 = 1920 - 128*it;          // rbase at jt=0, multiple of 128, >= 0
    int sigma = (rbase0 >> 7) % 3;

    load_block(rbase0);
    __syncthreads();
    pblock(sigma);                              // prolog: bottom half of first window

    float rs[4] = {0.f, 0.f, 0.f, 0.f};

    for (int jt = 0; jt < L_/128; jt++) {
        int j0 = jt * 128;
        int s_w = sigma + 1; if (s_w == 3) s_w = 0;
        __syncthreads();                        // prior epilogue done

        // K tile
        const uint4* Kg4 = (const uint4*)(g_Kbf + ((size_t)bh * L_ + j0) * D_);
        for (int t = tid; t < 1024; t += 256) {
            int r = t >> 3, c = t & 7;
            *(uint4*)(Ks + r*72 + c*8) = Kg4[t];
        }
        load_block(rbase0 + jt*128 + 128);      // new 128 Wp rows
        __syncthreads();

        pblock(s_w);                            // new P block -> ring

        // S = Q.K^T
        float accS[2][8][4] = {};
        #pragma unroll
        for (int kk = 0; kk < 4; kk++) {
            uint32_t a[2][4];
            #pragma unroll
            for (int mf = 0; mf < 2; mf++) {
                const __nv_bfloat16* qp = Qs + (wr*32 + mf*16 + g)*72 + kk*16 + qd*2;
                a[mf][0] = *(const uint32_t*)(qp);
                a[mf][1] = *(const uint32_t*)(qp + 8*72);
                a[mf][2] = *(const uint32_t*)(qp + 8);
                a[mf][3] = *(const uint32_t*)(qp + 8*72 + 8);
            }
            #pragma unroll
            for (int nf = 0; nf < 8; nf++) {
                const __nv_bfloat16* bp = Ks + (wc*64 + nf*8 + g)*72 + kk*16 + qd*2;
                uint32_t b0 = *(const uint32_t*)(bp);
                uint32_t b1 = *(const uint32_t*)(bp + 8);
                mma16816(accS[0][nf], a[0][0],a[0][1],a[0][2],a[0][3], b0,b1);
                mma16816(accS[1][nf], a[1][0],a[1][1],a[1][2],a[1][3], b0,b1);
            }
        }
        __syncthreads();                        // Psm ring stores visible

        // epilogue: s = S + P[row][pos], pos = 128*sigma + (j - row + 127)
        bool dt = (jt == it);
        int off = sigma*128 + 127;
        #pragma unroll
        for (int mf = 0; mf < 2; mf++) {
            int r0 = wr*32 + mf*16 + g, r1 = r0 + 8;
            const __nv_bfloat16* base0 = Psm + r0*PSP + off - r0;
            const __nv_bfloat16* base1 = Psm + r1*PSP + off - r1;
            #pragma unroll
            for (int nf = 0; nf < 8; nf++) {
                int j = wc*64 + nf*8 + qd*2;
                float t00 = accS[mf][nf][0] + __bfloat162float(base0[j]);
                float t01 = accS[mf][nf][1] + __bfloat162float(base0[j+1]);
                float t10 = accS[mf][nf][2] + __bfloat162float(base1[j]);
                float t11 = accS[mf][nf][3] + __bfloat162float(base1[j+1]);
                rs[mf*2+0] += fast_exp2(t00) + fast_exp2(t01);
                rs[mf*2+1] += fast_exp2(t10) + fast_exp2(t11);
                if (dt) {
                    if (j == r0)          sdArr[r0] = t00;
                    else if (j + 1 == r0) sdArr[r0] = t01;
                    if (j == r1)          sdArr[r1] = t10;
                    else if (j + 1 == r1) sdArr[r1] = t11;
                }
            }
        }
        sigma = s_w;
    }

    // reduce rs over quad lanes, then across the two column-half warps
    #pragma unroll
    for (int k = 0; k < 4; k++) {
        rs[k] += __shfl_xor_sync(0xffffffffu, rs[k], 1);
        rs[k] += __shfl_xor_sync(0xffffffffu, rs[k], 2);
    }
    if (qd == 0) {
        int base = wc*128 + wr*32;
        red[base + g]          = rs[0];
        red[base + g + 8]      = rs[1];
        red[base + 16 + g]     = rs[2];
        red[base + 16 + g + 8] = rs[3];
    }
    __syncthreads();
    if (tid < 128) {
        float r = red[tid] + red[128 + tid];
        g_Diag[(size_t)bh * L_ + i0 + tid] = fast_exp2(sdArr[tid]) / r;
    }
}

// ---------------- Kernel 3: O projection, bf16 HMMA, fused diag*V ---------------
__global__ __launch_bounds__(256, 2)
void gemm_out_bf16(const float* __restrict__ Wo, const float* __restrict__ bo,
                   float* __restrict__ out)
{
    __shared__ __nv_bfloat16 Ab[128*72];
    __shared__ __nv_bfloat16 Wb[128*72];

    int m0 = blockIdx.y * 128, n0 = blockIdx.x * 128;
    int tid = threadIdx.x, lane = tid & 31, w = tid >> 5;
    int wr = w >> 1, wc = w & 1, g = lane >> 2, qd = lane & 3;
    int rl = tid >> 4, c4 = (tid & 15) * 4;

    float acc[2][8][4] = {};

    for (int k0 = 0; k0 < H_; k0 += 64) {
        int h = k0 >> 6;                        // K-chunk == one head exactly
        __syncthreads();
        #pragma unroll
        for (int i = 0; i < 8; i++) {
            int r = i*16 + rl;
            int rg = m0 + r;
            int b = rg >> 11, l = rg & (L_ - 1);
            size_t vrow = (size_t)(b*NH + h) * L_ + l;
            float dg = g_Diag[vrow];
            float4 va = *(const float4*)&g_V[vrow * D_ + c4];
            float4 wv = *(const float4*)&Wo[(size_t)(n0 + r) * H_ + k0 + c4];
            __nv_bfloat162* pa = (__nv_bfloat162*)(Ab + r*72 + c4);
            pa[0] = __halves2bfloat162(__float2bfloat16(va.x*dg), __float2bfloat16(va.y*dg));
            pa[1] = __halves2bfloat162(__float2bfloat16(va.z*dg), __float2bfloat16(va.w*dg));
            __nv_bfloat162* pw = (__nv_bfloat162*)(Wb + r*72 + c4);
            pw[0] = __halves2bfloat162(__float2bfloat16(wv.x), __float2bfloat16(wv.y));
            pw[1] = __halves2bfloat162(__float2bfloat16(wv.z), __float2bfloat16(wv.w));
        }
        __syncthreads();
        #pragma unroll
        for (int kk = 0; kk < 4; kk++) {
            uint32_t a[2][4];
            #pragma unroll
            for (int mf = 0; mf < 2; mf++) {
                const __nv_bfloat16* qp = Ab + (wr*32 + mf*16 + g)*72 + kk*16 + qd*2;
                a[mf][0] = *(const uint32_t*)(qp);
                a[mf][1] = *(const uint32_t*)(qp + 8*72);
                a[mf][2] = *(const uint32_t*)(qp + 8);
                a[mf][3] = *(const uint32_t*)(qp + 8*72 + 8);
            }
            #pragma unroll
            for (int nf = 0; nf < 8; nf++) {
                const __nv_bfloat16* bp = Wb + (wc*64 + nf*8 + g)*72 + kk*16 + qd*2;
                uint32_t b0 = *(const uint32_t*)(bp);
                uint32_t b1 = *(const uint32_t*)(bp + 8);
                mma16816(acc[0][nf], a[0][0],a[0][1],a[0][2],a[0][3], b0,b1);
                mma16816(acc[1][nf], a[1][0],a[1][1],a[1][2],a[1][3], b0,b1);
            }
        }
    }

    #pragma unroll
    for (int mf = 0; mf < 2; mf++) {
        int rg = m0 + wr*32 + mf*16 + g;
        #pragma unroll
        for (int nf = 0; nf < 8; nf++) {
            int n = n0 + wc*64 + nf*8 + qd*2;
            float b0 = bo[n], b1 = bo[n+1];
            *(float2*)(out + (size_t)rg * H_ + n) =
                make_float2(acc[mf][nf][0] + b0, acc[mf][nf][1] + b1);
            *(float2*)(out + (size_t)(rg + 8) * H_ + n) =
                make_float2(acc[mf][nf][2] + b0, acc[mf][nf][3] + b1);
        }
    }
}

// ---------------- launch --------------------------------------------------------
extern "C" void kernel_launch(void* const* d_in, const int* in_sizes, int n_in,
                              void* d_out, int out_size)
{
    const float* q_in = (const float*)d_in[0];
    const float* k_in = (const float*)d_in[1];
    const float* v_in = (const float*)d_in[2];
    const float* Wq_w = (const float*)d_in[3];
    const float* Wq_b = (const float*)d_in[4];
    const float* Wk_w = (const float*)d_in[5];
    const float* Wk_b = (const float*)d_in[6];
    const float* Wv_w = (const float*)d_in[7];
    const float* Wv_b = (const float*)d_in[8];
    const float* Wo_w = (const float*)d_in[9];
    const float* Wo_b = (const float*)d_in[10];
    const float* Wp_w = (const float*)d_in[11];
    const float* Wp_b = (const float*)d_in[12];

    cudaFuncSetAttribute(attn_mma_kernel,
                         cudaFuncAttributeMaxDynamicSharedMemorySize, ATT_SMEM);

    gemm_qkv_bf16<<<dim3(H_/128, (B_*L_)/128, 3), 256>>>(
        q_in, k_in, v_in, Wq_w, Wq_b, Wk_w, Wk_b, Wv_w, Wv_b);

    wp_convert_kernel<<<(4096*D_)/256, 256>>>(Wp_w);

    attn_mma_kernel<<<dim3(L_/128, B_*NH), 256, ATT_SMEM>>>(Wp_b);

    gemm_out_bf16<<<dim3(H_/128, (B_*L_)/128), 256>>>(Wo_w, Wo_b, (float*)d_out);
}

// round 6
// speedup vs baseline: 7.8632x; 1.2876x over previous
#include <cuda_runtime.h>
#include <cuda_bf16.h>
#include <cstdint>

#define B_  4
#define L_  2048
#define H_  512
#define NH  8
#define D_  64

// ---------------- scratch (static device globals; no allocation) ----------------
__device__ __nv_bfloat16 g_Qbf[B_*NH*L_*D_];   // (b,h,l,d), scaled by 0.125*log2e
__device__ __nv_bfloat16 g_Kbf[B_*NH*L_*D_];
__device__ __nv_bfloat16 g_Wpbf[4096*D_];      // rows >= 4095 zero-padded
__device__ float g_V[B_*NH*L_*D_];             // fp32 head layout
__device__ float g_Diag[B_*NH*L_];             // softmax diagonal values

__device__ __forceinline__ float fast_exp2(float x) {
    float y; asm("ex2.approx.f32 %0, %1;" : "=f"(y) : "f"(x)); return y;
}
__device__ __forceinline__ void mma16816(float* c, uint32_t a0, uint32_t a1,
                                         uint32_t a2, uint32_t a3,
                                         uint32_t b0, uint32_t b1) {
    asm volatile(
        "mma.sync.aligned.m16n8k16.row.col.f32.bf16.bf16.f32 "
        "{%0,%1,%2,%3}, {%4,%5,%6,%7}, {%8,%9}, {%0,%1,%2,%3};"
        : "+f"(c[0]), "+f"(c[1]), "+f"(c[2]), "+f"(c[3])
        : "r"(a0), "r"(a1), "r"(a2), "r"(a3), "r"(b0), "r"(b1));
}
__device__ __forceinline__ uint32_t smem_u32(const void* p) {
    uint32_t a;
    asm("{ .reg .u64 t; cvta.to.shared.u64 t, %1; cvt.u32.u64 %0, t; }" : "=r"(a) : "l"(p));
    return a;
}
__device__ __forceinline__ void cp16(uint32_t s, const void* g) {
    asm volatile("cp.async.cg.shared.global [%0], [%1], 16;" :: "r"(s), "l"(g));
}
#define CP_COMMIT() asm volatile("cp.async.commit_group;" ::: "memory")

// ---------------- Kernel 1: QKV projections, bf16 HMMA --------------------------
__global__ __launch_bounds__(256, 2)
void gemm_qkv_bf16(const float* __restrict__ q_in, const float* __restrict__ k_in,
                   const float* __restrict__ v_in,
                   const float* __restrict__ Wq, const float* __restrict__ bq,
                   const float* __restrict__ Wk, const float* __restrict__ bk,
                   const float* __restrict__ Wv, const float* __restrict__ bv)
{
    __shared__ __nv_bfloat16 Ab[128*72];
    __shared__ __nv_bfloat16 Wb[128*72];

    int mode = blockIdx.z;
    const float *A, *W, *bias;
    if (mode == 0)      { A = q_in; W = Wq; bias = bq; }
    else if (mode == 1) { A = k_in; W = Wk; bias = bk; }
    else                { A = v_in; W = Wv; bias = bv; }

    int m0 = blockIdx.y * 128, n0 = blockIdx.x * 128;
    int tid = threadIdx.x, lane = tid & 31, w = tid >> 5;
    int wr = w >> 1, wc = w & 1, g = lane >> 2, qd = lane & 3;
    int rl = tid >> 4, c4 = (tid & 15) * 4;

    float acc[2][8][4] = {};

    for (int k0 = 0; k0 < H_; k0 += 64) {
        __syncthreads();
        #pragma unroll
        for (int i = 0; i < 8; i++) {
            int r = i*16 + rl;
            float4 va = *(const float4*)&A[(size_t)(m0 + r) * H_ + k0 + c4];
            float4 wv = *(const float4*)&W[(size_t)(n0 + r) * H_ + k0 + c4];
            __nv_bfloat162* pa = (__nv_bfloat162*)(Ab + r*72 + c4);
            pa[0] = __halves2bfloat162(__float2bfloat16(va.x), __float2bfloat16(va.y));
            pa[1] = __halves2bfloat162(__float2bfloat16(va.z), __float2bfloat16(va.w));
            __nv_bfloat162* pw = (__nv_bfloat162*)(Wb + r*72 + c4);
            pw[0] = __halves2bfloat162(__float2bfloat16(wv.x), __float2bfloat16(wv.y));
            pw[1] = __halves2bfloat162(__float2bfloat16(wv.z), __float2bfloat16(wv.w));
        }
        __syncthreads();
        #pragma unroll
        for (int kk = 0; kk < 4; kk++) {
            uint32_t a[2][4];
            #pragma unroll
            for (int mf = 0; mf < 2; mf++) {
                const __nv_bfloat16* qp = Ab + (wr*32 + mf*16 + g)*72 + kk*16 + qd*2;
                a[mf][0] = *(const uint32_t*)(qp);
                a[mf][1] = *(const uint32_t*)(qp + 8*72);
                a[mf][2] = *(const uint32_t*)(qp + 8);
                a[mf][3] = *(const uint32_t*)(qp + 8*72 + 8);
            }
            #pragma unroll
            for (int nf = 0; nf < 8; nf++) {
                const __nv_bfloat16* bp = Wb + (wc*64 + nf*8 + g)*72 + kk*16 + qd*2;
                uint32_t b0 = *(const uint32_t*)(bp);
                uint32_t b1 = *(const uint32_t*)(bp + 8);
                mma16816(acc[0][nf], a[0][0],a[0][1],a[0][2],a[0][3], b0,b1);
                mma16816(acc[1][nf], a[1][0],a[1][1],a[1][2],a[1][3], b0,b1);
            }
        }
    }

    const float qs = 0.125f * 1.4426950408889634f;
    #pragma unroll
    for (int mf = 0; mf < 2; mf++) {
        int rg = m0 + wr*32 + mf*16 + g;
        int b = rg >> 11, l = rg & (L_ - 1);
        #pragma unroll
        for (int nf = 0; nf < 8; nf++) {
            int n = n0 + wc*64 + nf*8 + qd*2;
            int h = n >> 6, d = n & 63;
            float b0 = bias[n], b1 = bias[n+1];
            float v00 = acc[mf][nf][0] + b0, v01 = acc[mf][nf][1] + b1;
            float v10 = acc[mf][nf][2] + b0, v11 = acc[mf][nf][3] + b1;
            size_t o0 = ((size_t)(b*NH + h) * L_ + l) * D_ + d;
            size_t o1 = o0 + 8*D_;
            if (mode == 0) {
                *(__nv_bfloat162*)(g_Qbf + o0) =
                    __halves2bfloat162(__float2bfloat16(v00*qs), __float2bfloat16(v01*qs));
                *(__nv_bfloat162*)(g_Qbf + o1) =
                    __halves2bfloat162(__float2bfloat16(v10*qs), __float2bfloat16(v11*qs));
            } else if (mode == 1) {
                *(__nv_bfloat162*)(g_Kbf + o0) =
                    __halves2bfloat162(__float2bfloat16(v00), __float2bfloat16(v01));
                *(__nv_bfloat162*)(g_Kbf + o1) =
                    __halves2bfloat162(__float2bfloat16(v10), __float2bfloat16(v11));
            } else {
                *(float2*)(g_V + o0) = make_float2(v00, v01);
                *(float2*)(g_V + o1) = make_float2(v10, v11);
            }
        }
    }
}

// ---------------- Kernel 1b: convert Wp to padded bf16 --------------------------
__global__ __launch_bounds__(256)
void wp_convert_kernel(const float* __restrict__ Wp)
{
    int idx = blockIdx.x * 256 + threadIdx.x;   // < 4096*64
    int r = idx >> 6;
    g_Wpbf[idx] = __float2bfloat16(r < 2*L_ - 1 ? Wp[idx] : 0.f);
}

// ---------------- Kernel 2: HMMA score pass, rolling-P ring, async pipeline -----
// 512 threads (16 warps: wr 0..3 rows, wc 0..3 cols). cp.async double-buffered
// K and Wp tiles. Ring slot of Wp-row r = 128*((r>>7)%3)+(r&127); slot 0 mirrored
// at cols [384,512) so gather pos = 128*sigma + (j-row+127) never wraps.
#define PSP 520
#define AOFF_KS0 18432
#define AOFF_KS1 36864
#define AOFF_WS0 55296
#define AOFF_WS1 73728
#define AOFF_PS  92160
#define AOFF_WB  225280
#define AOFF_SD  226304
#define AOFF_RED 226816
#define ATT_SMEM 228864

__global__ __launch_bounds__(512, 1)
void attn_mma_kernel(const float* __restrict__ Wpb)
{
    extern __shared__ char smc[];
    __nv_bfloat16* Qs  = (__nv_bfloat16*)(smc);
    __nv_bfloat16* Psm = (__nv_bfloat16*)(smc + AOFF_PS);
    float* wbn   = (float*)(smc + AOFF_WB);    // [2][128]
    float* sdArr = (float*)(smc + AOFF_SD);
    float* red   = (float*)(smc + AOFF_RED);   // [4][128]

    const int tid = threadIdx.x;
    const int lane = tid & 31, w = tid >> 5;
    const int wr = w >> 2, wc = w & 3;
    const int g = lane >> 2, qd = lane & 3;
    const int bh = blockIdx.y, it = blockIdx.x;
    const int i0 = it * 128;
    const int rbase0 = 1920 - 128*it;

    const uint32_t ks_s[2] = { smem_u32(smc + AOFF_KS0), smem_u32(smc + AOFF_KS1) };
    const uint32_t ws_s[2] = { smem_u32(smc + AOFF_WS0), smem_u32(smc + AOFF_WS1) };

    // async copy of a 128x64 bf16 tile (row-major, pitch 72) into smem buffer
    auto cp_tile = [&](uint32_t sbase, const __nv_bfloat16* gsrc) {
        const uint4* g4 = (const uint4*)gsrc;
        #pragma unroll
        for (int t = tid; t < 1024; t += 512) {
            int r = t >> 3, c = t & 7;
            cp16(sbase + (r*72 + c*8)*2, g4 + t);
        }
    };

    // ---- prolog: Q (plain), K tile 0 -> KS0, W(rbase0) -> WS1, W(rbase0+128) -> WS0
    {
        const uint4* Qg4 = (const uint4*)(g_Qbf + ((size_t)bh * L_ + i0) * D_);
        for (int t = tid; t < 1024; t += 512) {
            int r = t >> 3, c = t & 7;
            *(uint4*)(Qs + r*72 + c*8) = Qg4[t];
        }
    }
    cp_tile(ks_s[0], g_Kbf + (size_t)bh * L_ * D_);
    cp_tile(ws_s[1], g_Wpbf + (size_t)rbase0 * D_);
    cp_tile(ws_s[0], g_Wpbf + (size_t)(rbase0 + 128) * D_);
    CP_COMMIT();
    if (tid < 128) {
        wbn[128 + tid] = Wpb[rbase0 + tid] * 1.4426950408889634f;
        wbn[tid]       = Wpb[rbase0 + 128 + tid] * 1.4426950408889634f;
    }
    asm volatile("cp.async.wait_group 0;" ::: "memory");
    __syncthreads();

    // compute 128x128 P block from Ws buffer, store (biased, bf16) into ring slot
    auto pblock = [&](const __nv_bfloat16* Ws, const float* wb, int slot) {
        float accP[2][4][4] = {};
        #pragma unroll
        for (int kk = 0; kk < 4; kk++) {
            uint32_t a[2][4];
            #pragma unroll
            for (int mf = 0; mf < 2; mf++) {
                const __nv_bfloat16* qp = Qs + (wr*32 + mf*16 + g)*72 + kk*16 + qd*2;
                a[mf][0] = *(const uint32_t*)(qp);
                a[mf][1] = *(const uint32_t*)(qp + 8*72);
                a[mf][2] = *(const uint32_t*)(qp + 8);
                a[mf][3] = *(const uint32_t*)(qp + 8*72 + 8);
            }
            #pragma unroll
            for (int nf = 0; nf < 4; nf++) {
                const __nv_bfloat16* bp = Ws + (wc*32 + nf*8 + g)*72 + kk*16 + qd*2;
                uint32_t b0 = *(const uint32_t*)(bp);
                uint32_t b1 = *(const uint32_t*)(bp + 8);
                mma16816(accP[0][nf], a[0][0],a[0][1],a[0][2],a[0][3], b0,b1);
                mma16816(accP[1][nf], a[1][0],a[1][1],a[1][2],a[1][3], b0,b1);
            }
        }
        int pb = slot * 128;
        #pragma unroll
        for (int mf = 0; mf < 2; mf++) {
            int r0 = wr*32 + mf*16 + g, r1 = r0 + 8;
            #pragma unroll
            for (int nf = 0; nf < 4; nf++) {
                int c = wc*32 + nf*8 + qd*2;
                float b0 = wb[c], b1 = wb[c+1];
                __nv_bfloat16 v00 = __float2bfloat16(accP[mf][nf][0] + b0);
                __nv_bfloat16 v01 = __float2bfloat16(accP[mf][nf][1] + b1);
                __nv_bfloat16 v10 = __float2bfloat16(accP[mf][nf][2] + b0);
                __nv_bfloat16 v11 = __float2bfloat16(accP[mf][nf][3] + b1);
                Psm[r0*PSP + pb + c]     = v00;
                Psm[r0*PSP + pb + c + 1] = v01;
                Psm[r1*PSP + pb + c]     = v10;
                Psm[r1*PSP + pb + c + 1] = v11;
                if (slot == 0) {
                    Psm[r0*PSP + 384 + c]     = v00;
                    Psm[r0*PSP + 384 + c + 1] = v01;
                    Psm[r1*PSP + 384 + c]     = v10;
                    Psm[r1*PSP + 384 + c + 1] = v11;
                }
            }
        }
    };

    int sigma = (rbase0 >> 7) % 3;
    pblock((const __nv_bfloat16*)(smc + AOFF_WS1), wbn + 128, sigma);  // W(rbase0)

    float rs[4] = {0.f, 0.f, 0.f, 0.f};

    for (int jt = 0; jt < L_/128; jt++) {
        int cur = jt & 1, nxt = cur ^ 1;
        int s_w = sigma + 1; if (s_w == 3) s_w = 0;
        __syncthreads();                        // prior epilogue reads done

        // prefetch tile jt+1: K(jt+1) and W(rbase0+(jt+2)*128)
        if (jt < 15) {
            cp_tile(ks_s[nxt], g_Kbf + ((size_t)bh * L_ + (jt+1)*128) * D_);
            cp_tile(ws_s[nxt], g_Wpbf + (size_t)(rbase0 + (jt+2)*128) * D_);
            CP_COMMIT();
            if (tid < 128) {
                int idx = rbase0 + (jt+2)*128 + tid;
                wbn[nxt*128 + tid] = (idx < 2*L_ - 1)
                                   ? Wpb[idx] * 1.4426950408889634f : 0.f;
            }
            asm volatile("cp.async.wait_group 1;" ::: "memory");
        } else {
            asm volatile("cp.async.wait_group 0;" ::: "memory");
        }
        __syncthreads();                        // buffers[cur] visible to all

        const __nv_bfloat16* Ks = (const __nv_bfloat16*)(smc + (cur ? AOFF_KS1 : AOFF_KS0));
        const __nv_bfloat16* Ws = (const __nv_bfloat16*)(smc + (cur ? AOFF_WS1 : AOFF_WS0));

        pblock(Ws, wbn + cur*128, s_w);         // new P block -> ring

        // S = Q.K^T (warp: 32 rows x 32 cols)
        float accS[2][4][4] = {};
        #pragma unroll
        for (int kk = 0; kk < 4; kk++) {
            uint32_t a[2][4];
            #pragma unroll
            for (int mf = 0; mf < 2; mf++) {
                const __nv_bfloat16* qp = Qs + (wr*32 + mf*16 + g)*72 + kk*16 + qd*2;
                a[mf][0] = *(const uint32_t*)(qp);
                a[mf][1] = *(const uint32_t*)(qp + 8*72);
                a[mf][2] = *(const uint32_t*)(qp + 8);
                a[mf][3] = *(const uint32_t*)(qp + 8*72 + 8);
            }
            #pragma unroll
            for (int nf = 0; nf < 4; nf++) {
                const __nv_bfloat16* bp = Ks + (wc*32 + nf*8 + g)*72 + kk*16 + qd*2;
                uint32_t b0 = *(const uint32_t*)(bp);
                uint32_t b1 = *(const uint32_t*)(bp + 8);
                mma16816(accS[0][nf], a[0][0],a[0][1],a[0][2],a[0][3], b0,b1);
                mma16816(accS[1][nf], a[1][0],a[1][1],a[1][2],a[1][3], b0,b1);
            }
        }
        __syncthreads();                        // ring stores visible

        // epilogue: s = S + P[row][128*sigma + (j - row + 127)]
        bool dt = (jt == it);
        int off = sigma*128 + 127;
        #pragma unroll
        for (int mf = 0; mf < 2; mf++) {
            int r0 = wr*32 + mf*16 + g, r1 = r0 + 8;
            const __nv_bfloat16* base0 = Psm + r0*PSP + off - r0;
            const __nv_bfloat16* base1 = Psm + r1*PSP + off - r1;
            #pragma unroll
            for (int nf = 0; nf < 4; nf++) {
                int j = wc*32 + nf*8 + qd*2;
                float t00 = accS[mf][nf][0] + __bfloat162float(base0[j]);
                float t01 = accS[mf][nf][1] + __bfloat162float(base0[j+1]);
                float t10 = accS[mf][nf][2] + __bfloat162float(base1[j]);
                float t11 = accS[mf][nf][3] + __bfloat162float(base1[j+1]);
                rs[mf*2+0] += fast_exp2(t00) + fast_exp2(t01);
                rs[mf*2+1] += fast_exp2(t10) + fast_exp2(t11);
                if (dt) {
                    if (j == r0)          sdArr[r0] = t00;
                    else if (j + 1 == r0) sdArr[r0] = t01;
                    if (j == r1)          sdArr[r1] = t10;
                    else if (j + 1 == r1) sdArr[r1] = t11;
                }
            }
        }
        sigma = s_w;
    }

    // reduce: quad lanes (shfl), then across the 4 column warps via smem
    #pragma unroll
    for (int k = 0; k < 4; k++) {
        rs[k] += __shfl_xor_sync(0xffffffffu, rs[k], 1);
        rs[k] += __shfl_xor_sync(0xffffffffu, rs[k], 2);
    }
    if (qd == 0) {
        int base = wc*128 + wr*32 + g;
        red[base]      = rs[0];
        red[base + 8]  = rs[1];
        red[base + 16] = rs[2];
        red[base + 24] = rs[3];
    }
    __syncthreads();
    if (tid < 128) {
        float r = red[tid] + red[128 + tid] + red[256 + tid] + red[384 + tid];
        g_Diag[(size_t)bh * L_ + i0 + tid] = fast_exp2(sdArr[tid]) / r;
    }
}

// ---------------- Kernel 3: O projection, bf16 HMMA, fused diag*V ---------------
__global__ __launch_bounds__(256, 2)
void gemm_out_bf16(const float* __restrict__ Wo, const float* __restrict__ bo,
                   float* __restrict__ out)
{
    __shared__ __nv_bfloat16 Ab[128*72];
    __shared__ __nv_bfloat16 Wb[128*72];

    int m0 = blockIdx.y * 128, n0 = blockIdx.x * 128;
    int tid = threadIdx.x, lane = tid & 31, w = tid >> 5;
    int wr = w >> 1, wc = w & 1, g = lane >> 2, qd = lane & 3;
    int rl = tid >> 4, c4 = (tid & 15) * 4;

    float acc[2][8][4] = {};

    for (int k0 = 0; k0 < H_; k0 += 64) {
        int h = k0 >> 6;
        __syncthreads();
        #pragma unroll
        for (int i = 0; i < 8; i++) {
            int r = i*16 + rl;
            int rg = m0 + r;
            int b = rg >> 11, l = rg & (L_ - 1);
            size_t vrow = (size_t)(b*NH + h) * L_ + l;
            float dg = g_Diag[vrow];
            float4 va = *(const float4*)&g_V[vrow * D_ + c4];
            float4 wv = *(const float4*)&Wo[(size_t)(n0 + r) * H_ + k0 + c4];
            __nv_bfloat162* pa = (__nv_bfloat162*)(Ab + r*72 + c4);
            pa[0] = __halves2bfloat162(__float2bfloat16(va.x*dg), __float2bfloat16(va.y*dg));
            pa[1] = __halves2bfloat162(__float2bfloat16(va.z*dg), __float2bfloat16(va.w*dg));
            __nv_bfloat162* pw = (__nv_bfloat162*)(Wb + r*72 + c4);
            pw[0] = __halves2bfloat162(__float2bfloat16(wv.x), __float2bfloat16(wv.y));
            pw[1] = __halves2bfloat162(__float2bfloat16(wv.z), __float2bfloat16(wv.w));
        }
        __syncthreads();
        #pragma unroll
        for (int kk = 0; kk < 4; kk++) {
            uint32_t a[2][4];
            #pragma unroll
            for (int mf = 0; mf < 2; mf++) {
                const __nv_bfloat16* qp = Ab + (wr*32 + mf*16 + g)*72 + kk*16 + qd*2;
                a[mf][0] = *(const uint32_t*)(qp);
                a[mf][1] = *(const uint32_t*)(qp + 8*72);
                a[mf][2] = *(const uint32_t*)(qp + 8);
                a[mf][3] = *(const uint32_t*)(qp + 8*72 + 8);
            }
            #pragma unroll
            for (int nf = 0; nf < 8; nf++) {
                const __nv_bfloat16* bp = Wb + (wc*64 + nf*8 + g)*72 + kk*16 + qd*2;
                uint32_t b0 = *(const uint32_t*)(bp);
                uint32_t b1 = *(const uint32_t*)(bp + 8);
                mma16816(acc[0][nf], a[0][0],a[0][1],a[0][2],a[0][3], b0,b1);
                mma16816(acc[1][nf], a[1][0],a[1][1],a[1][2],a[1][3], b0,b1);
            }
        }
    }

    #pragma unroll
    for (int mf = 0; mf < 2; mf++) {
        int rg = m0 + wr*32 + mf*16 + g;
        #pragma unroll
        for (int nf = 0; nf < 8; nf++) {
            int n = n0 + wc*64 + nf*8 + qd*2;
            float b0 = bo[n], b1 = bo[n+1];
            *(float2*)(out + (size_t)rg * H_ + n) =
                make_float2(acc[mf][nf][0] + b0, acc[mf][nf][1] + b1);
            *(float2*)(out + (size_t)(rg + 8) * H_ + n) =
                make_float2(acc[mf][nf][2] + b0, acc[mf][nf][3] + b1);
        }
    }
}

// ---------------- launch --------------------------------------------------------
extern "C" void kernel_launch(void* const* d_in, const int* in_sizes, int n_in,
                              void* d_out, int out_size)
{
    const float* q_in = (const float*)d_in[0];
    const float* k_in = (const float*)d_in[1];
    const float* v_in = (const float*)d_in[2];
    const float* Wq_w = (const float*)d_in[3];
    const float* Wq_b = (const float*)d_in[4];
    const float* Wk_w = (const float*)d_in[5];
    const float* Wk_b = (const float*)d_in[6];
    const float* Wv_w = (const float*)d_in[7];
    const float* Wv_b = (const float*)d_in[8];
    const float* Wo_w = (const float*)d_in[9];
    const float* Wo_b = (const float*)d_in[10];
    const float* Wp_w = (const float*)d_in[11];
    const float* Wp_b = (const float*)d_in[12];

    cudaFuncSetAttribute(attn_mma_kernel,
                         cudaFuncAttributeMaxDynamicSharedMemorySize, ATT_SMEM);

    gemm_qkv_bf16<<<dim3(H_/128, (B_*L_)/128, 3), 256>>>(
        q_in, k_in, v_in, Wq_w, Wq_b, Wk_w, Wk_b, Wv_w, Wv_b);

    wp_convert_kernel<<<(4096*D_)/256, 256>>>(Wp_w);

    attn_mma_kernel<<<dim3(L_/128, B_*NH), 512, ATT_SMEM>>>(Wp_b);

    gemm_out_bf16<<<dim3(H_/128, (B_*L_)/128), 256>>>(Wo_w, Wo_b, (float*)d_out);
}